// round 10
// baseline (speedup 1.0000x reference)
#include <cuda_runtime.h>
#include <cuda_fp16.h>
#include <cstdint>

// ---------------- problem constants ----------------
#define SEQ_LEN   16384
#define T_OUT     16376
#define C_IN      64
#define N_F       64
#define K_W       9
#define N_BATCH   32

#define TILE_M    512
#define TILES_PB  (SEQ_LEN / TILE_M)       // 32
#define N_TILES   (N_BATCH * TILES_PB)     // 1024
#define GRID_CTAS 148                      // 1 persistent CTA per SM
#define THREADS   256                      // 8 warps

// ---------------- SMEM layout ----------------
// Weights: 64 filter rows, 576 fp16 each, padded stride 1168 B
// (73 x 16B chunks, 73 % 8 == 1 -> conflict-free ldmatrix across rows).
#define WSTRIDE    1168
#define SMEM_W     0
#define SMEM_BIAS  (64 * WSTRIDE)                // 74752
#define SMEM_X0    (SMEM_BIAS + 256)             // 75008 (128B aligned)
#define X_ROWS     (TILE_M + 8)                  // 520 rows (tap halo)
#define XBUF_BYTES (X_ROWS * 128)                // 66560
#define SMEM_X1    (SMEM_X0 + XBUF_BYTES)
#define SMEM_TOTAL (SMEM_X1 + XBUF_BYTES)        // 208128 B -> 1 CTA/SM

#define N_CHUNKS   (X_ROWS * 8)                  // 4160 16B-chunks per X buffer

__device__ __forceinline__ uint32_t smem_to_u32(const void* smem_ptr) {
    uint32_t addr;
    asm("{ .reg .u64 tmp; cvta.to.shared.u64 tmp, %1; cvt.u32.u64 %0, tmp; }"
        : "=r"(addr) : "l"(smem_ptr));
    return addr;
}

#define LDSM_X4(r0, r1, r2, r3, addr) \
    asm volatile("ldmatrix.sync.aligned.m8n8.x4.shared.b16 {%0,%1,%2,%3}, [%4];" \
        : "=r"(r0), "=r"(r1), "=r"(r2), "=r"(r3) : "r"(addr))

#define MMA_16816(acc, a0, a1, a2, a3, b0, b1) \
    asm volatile( \
        "mma.sync.aligned.m16n8k16.row.col.f32.f16.f16.f32 " \
        "{%0,%1,%2,%3}, {%4,%5,%6,%7}, {%8,%9}, {%0,%1,%2,%3};" \
        : "+f"((acc)[0]), "+f"((acc)[1]), "+f"((acc)[2]), "+f"((acc)[3]) \
        : "r"(a0), "r"(a1), "r"(a2), "r"(a3), "r"(b0), "r"(b1))

// One staging iteration: thread's s-th 16B chunk of the next tile's X buffer.
// fp32 gmem -> fp16 SMEM with XOR-(row&7) swizzle on the 8 chunks of a row.
__device__ __forceinline__ void stage_iter(char* xbuf, const float* xb_next,
                                           int tb_next, int s, int tid)
{
    const int ci = tid + (s << 8);         // s*256 threads
    if (ci < N_CHUNKS) {
        const int r  = ci >> 3;
        const int c8 = ci & 7;
        int rg = tb_next + r;
        if (rg > SEQ_LEN - 1) rg = SEQ_LEN - 1;   // halo clamp -> discarded t only
        const float4* src = (const float4*)(xb_next + (size_t)rg * 64 + c8 * 8);
        float4 v0 = src[0];
        float4 v1 = src[1];
        __half2 h0 = __floats2half2_rn(v0.x, v0.y);
        __half2 h1 = __floats2half2_rn(v0.z, v0.w);
        __half2 h2 = __floats2half2_rn(v1.x, v1.y);
        __half2 h3 = __floats2half2_rn(v1.z, v1.w);
        uint4 pk;
        pk.x = *(uint32_t*)&h0; pk.y = *(uint32_t*)&h1;
        pk.z = *(uint32_t*)&h2; pk.w = *(uint32_t*)&h3;
        *(uint4*)(xbuf + r * 128 + ((c8 ^ (r & 7)) * 16)) = pk;
    }
}

// ---------------- kernel ----------------
// 8 warps; warp w owns output rows [w*64, w*64+64) of the 512-row tile and all
// 64 filters (traffic-optimal split). X is double-buffered: tile i+1 is staged
// (LDG+cvt+STS) interleaved into tile i's tap loop, hiding DRAM latency under
// HMMA issue. One __syncthreads per tile.
__global__ void __launch_bounds__(THREADS)
conv1d_hmma_kernel(const float* __restrict__ x,
                   const float* __restrict__ w,
                   const float* __restrict__ bias,
                   float* __restrict__ out)
{
    extern __shared__ __align__(16) char smem[];
    const uint32_t smem_u = smem_to_u32(smem);
    const int tid  = threadIdx.x;
    const int lane = tid & 31;
    const int warp = tid >> 5;

    // ---- one-time: weights fp32 -> fp16 into padded SMEM rows ----
    for (int idx = tid; idx < 64 * 72; idx += THREADS) {
        const int f = idx / 72;
        const int j = idx - f * 72;
        const float4* s = (const float4*)(w + (size_t)f * 576 + (size_t)j * 8);
        float4 v0 = s[0];
        float4 v1 = s[1];
        __half2 h0 = __floats2half2_rn(v0.x, v0.y);
        __half2 h1 = __floats2half2_rn(v0.z, v0.w);
        __half2 h2 = __floats2half2_rn(v1.x, v1.y);
        __half2 h3 = __floats2half2_rn(v1.z, v1.w);
        uint4 pk;
        pk.x = *(uint32_t*)&h0; pk.y = *(uint32_t*)&h1;
        pk.z = *(uint32_t*)&h2; pk.w = *(uint32_t*)&h3;
        *(uint4*)(smem + SMEM_W + f * WSTRIDE + j * 16) = pk;
    }
    if (tid < N_F) ((float*)(smem + SMEM_BIAS))[tid] = bias[tid];

    // ---- per-lane ldmatrix bases ----
    // B (weights): x4 covers an n-tile pair; lanes 0-15 -> even nt (k-half via
    // bit3 of lane), lanes 16-31 -> odd nt.
    const uint32_t b_lanebase = smem_u + SMEM_W
        + (uint32_t)((((lane >> 4) * 8 + (lane & 7)) * WSTRIDE) + ((lane >> 3) & 1) * 16);
    // A (x): lanes 0-15 -> rows, col-half 0; lanes 16-31 -> col-half 1.
    const int arow0 = warp * 64 + (lane & 15);
    const int ahalf = lane >> 4;

    const int tile0 = blockIdx.x;
    if (tile0 >= N_TILES) return;

    // ---- prologue: stage first tile into buffer 0 ----
    {
        const int batch = tile0 / TILES_PB;
        const int tb    = (tile0 % TILES_PB) * TILE_M;
        const float* xb = x + (size_t)batch * (SEQ_LEN * C_IN);
        for (int s = 0; s < 17; s++)
            stage_iter(smem + SMEM_X0, xb, tb, s, tid);
    }
    __syncthreads();

    int cur = 0;
    for (int tile = tile0; tile < N_TILES; tile += GRID_CTAS) {
        const int batch = tile / TILES_PB;
        const int tb    = (tile % TILES_PB) * TILE_M;

        // next tile to prefetch (double buffer)
        const int  tile_n   = tile + GRID_CTAS;
        const bool has_next = (tile_n < N_TILES);
        const int  batch_n  = has_next ? (tile_n / TILES_PB) : 0;
        const int  tb_n     = has_next ? ((tile_n % TILES_PB) * TILE_M) : 0;
        const float* xb_n   = x + (size_t)batch_n * (SEQ_LEN * C_IN);
        char* xbuf_next     = smem + (cur ? SMEM_X0 : SMEM_X1);
        const uint32_t xoff = cur ? SMEM_X1 : SMEM_X0;

        // ---- mainloop ----
        float acc[4][8][4];
        #pragma unroll
        for (int mt = 0; mt < 4; mt++)
            #pragma unroll
            for (int nt = 0; nt < 8; nt++)
                #pragma unroll
                for (int i = 0; i < 4; i++)
                    acc[mt][nt][i] = 0.0f;

        #pragma unroll
        for (int tap = 0; tap < K_W; tap++) {
            // interleave 2 staging iterations per tap (17 total needed, 18 slots)
            if (has_next) {
                stage_iter(xbuf_next, xb_n, tb_n, 2 * tap, tid);
                if (2 * tap + 1 < 17)
                    stage_iter(xbuf_next, xb_n, tb_n, 2 * tap + 1, tid);
            }
            #pragma unroll
            for (int kc = 0; kc < 4; kc++) {
                // B fragments: all 8 n-tiles for this (tap, kc)
                uint32_t bfr[8][2];
                const uint32_t bko = (uint32_t)((tap * 64 + kc * 16) * 2);
                #pragma unroll
                for (int p = 0; p < 4; p++) {
                    LDSM_X4(bfr[2 * p][0], bfr[2 * p][1],
                            bfr[2 * p + 1][0], bfr[2 * p + 1][1],
                            b_lanebase + (uint32_t)(p * 16 * WSTRIDE) + bko);
                }
                // A per m-tile, then 8 MMAs against held B frags
                #pragma unroll
                for (int mt = 0; mt < 4; mt++) {
                    const int row = arow0 + mt * 16 + tap;
                    const uint32_t chunk = (uint32_t)((kc * 2 + ahalf) ^ (row & 7));
                    const uint32_t aaddr = smem_u + xoff
                        + (uint32_t)(row * 128) + chunk * 16;
                    uint32_t a0, a1, a2, a3;
                    LDSM_X4(a0, a1, a2, a3, aaddr);
                    #pragma unroll
                    for (int nt = 0; nt < 8; nt++) {
                        MMA_16816(acc[mt][nt], a0, a1, a2, a3,
                                  bfr[nt][0], bfr[nt][1]);
                    }
                }
            }
        }

        // ---- epilogue: bias add + fp32 store (registers + gmem only) ----
        const int trow0   = tb + warp * 64 + (lane >> 2);
        const int colbase = (lane & 3) * 2;
        const float* bsm  = (const float*)(smem + SMEM_BIAS);
        #pragma unroll
        for (int mt = 0; mt < 4; mt++) {
            #pragma unroll
            for (int h = 0; h < 2; h++) {
                const int t = trow0 + mt * 16 + h * 8;
                if (t < T_OUT) {
                    float* op = out + ((size_t)batch * T_OUT + t) * N_F;
                    #pragma unroll
                    for (int nt = 0; nt < 8; nt++) {
                        const int col = nt * 8 + colbase;
                        const float2 bv = *(const float2*)(bsm + col);
                        float2 r2;
                        r2.x = acc[mt][nt][h * 2 + 0] + bv.x;
                        r2.y = acc[mt][nt][h * 2 + 1] + bv.y;
                        *(float2*)(op + col) = r2;
                    }
                }
            }
        }

        // staged writes visible to all / current buffer reads complete
        __syncthreads();
        cur ^= 1;
    }
}

// ---------------- launch ----------------
extern "C" void kernel_launch(void* const* d_in, const int* in_sizes, int n_in,
                              void* d_out, int out_size)
{
    const float* x    = (const float*)d_in[0];
    const float* w    = (const float*)d_in[1];
    const float* bias = (const float*)d_in[2];
    float* out        = (float*)d_out;

    cudaFuncSetAttribute(conv1d_hmma_kernel,
                         cudaFuncAttributeMaxDynamicSharedMemorySize, SMEM_TOTAL);
    conv1d_hmma_kernel<<<GRID_CTAS, THREADS, SMEM_TOTAL>>>(x, w, bias, out);
}

// round 11
// speedup vs baseline: 1.0672x; 1.0672x over previous
#include <cuda_runtime.h>
#include <cuda_fp16.h>
#include <cstdint>

// ---------------- problem constants ----------------
#define SEQ_LEN   16384
#define T_OUT     16376
#define C_IN      64
#define N_F       64
#define K_W       9
#define N_BATCH   32

#define TILE_M    256
#define TILES_PB  (SEQ_LEN / TILE_M)       // 64
#define N_TILES   (N_BATCH * TILES_PB)     // 2048
#define GRID_CTAS 296                      // 148 SMs * 2 persistent CTAs
#define THREADS   128                      // 4 warps

// ---------------- SMEM layout (W evicted to gmem-scratch/L1) ----------------
#define SMEM_BIAS  0                             // 256 B
#define SMEM_X0    256
#define X_ROWS     (TILE_M + 8)                  // 264 rows (tap halo)
#define XBUF_BYTES (X_ROWS * 128)                // 33792
#define SMEM_X1    (SMEM_X0 + XBUF_BYTES)
#define SMEM_TOTAL (SMEM_X1 + XBUF_BYTES)       // 67840 B -> 2 CTAs/SM

#define N_CHUNKS   (X_ROWS * 8)                  // 2112 16B-chunks per X buffer
#define STAGE_ITERS ((N_CHUNKS + THREADS - 1) / THREADS)   // 17

// ---------------- W fragment scratch (gmem, L1-resident) ----------------
// Layout: [sp(18)][j(8)][lane(32)] x 16B, sp = kstep pair, j = n-tile.
// 16B = { b0(s=2sp), b1(2sp), b0(2sp+1), b1(2sp+1) } as half2 each.
__device__ uint4 g_wfrag[18 * 8 * 32];           // 73728 B

__device__ __forceinline__ uint32_t smem_to_u32(const void* smem_ptr) {
    uint32_t addr;
    asm("{ .reg .u64 tmp; cvta.to.shared.u64 tmp, %1; cvt.u32.u64 %0, tmp; }"
        : "=r"(addr) : "l"(smem_ptr));
    return addr;
}

#define LDSM_X4(r0, r1, r2, r3, addr) \
    asm volatile("ldmatrix.sync.aligned.m8n8.x4.shared.b16 {%0,%1,%2,%3}, [%4];" \
        : "=r"(r0), "=r"(r1), "=r"(r2), "=r"(r3) : "r"(addr))

#define MMA_16816(acc, a0, a1, a2, a3, b0, b1) \
    asm volatile( \
        "mma.sync.aligned.m16n8k16.row.col.f32.f16.f16.f32 " \
        "{%0,%1,%2,%3}, {%4,%5,%6,%7}, {%8,%9}, {%0,%1,%2,%3};" \
        : "+f"((acc)[0]), "+f"((acc)[1]), "+f"((acc)[2]), "+f"((acc)[3]) \
        : "r"(a0), "r"(a1), "r"(a2), "r"(a3), "r"(b0), "r"(b1))

// ---------------- init kernel: pack W into fragment-major fp16 scratch ----------------
// mma.m16n8k16 B fragment (col-major KxN): lane holds b0 = (k=(lane%4)*2..+1,
// n=lane/4), b1 = (k+8, n). Global k = tap*64 + kc*16 + kk  (s = tap*4+kc).
__global__ void conv1d_wfrag_init(const float* __restrict__ w)
{
    const int idx  = blockIdx.x * 256 + threadIdx.x;   // 0..4607
    if (idx >= 18 * 8 * 32) return;
    const int lane = idx & 31;
    const int j    = (idx >> 5) & 7;
    const int sp   = idx >> 8;
    const int n    = j * 8 + (lane >> 2);
    uint32_t pk[4];
    #pragma unroll
    for (int e = 0; e < 2; e++) {
        const int s   = 2 * sp + e;
        const int tap = s >> 2;
        const int kc  = s & 3;
        const int c0  = kc * 16 + (lane & 3) * 2;
        const float* wr = w + (size_t)n * (K_W * C_IN) + tap * C_IN;
        __half2 b0 = __floats2half2_rn(wr[c0],     wr[c0 + 1]);
        __half2 b1 = __floats2half2_rn(wr[c0 + 8], wr[c0 + 9]);
        pk[2 * e]     = *(uint32_t*)&b0;
        pk[2 * e + 1] = *(uint32_t*)&b1;
    }
    uint4 v; v.x = pk[0]; v.y = pk[1]; v.z = pk[2]; v.w = pk[3];
    g_wfrag[idx] = v;
}

// One staging iteration: thread's s-th 16B chunk of the next tile's X buffer.
__device__ __forceinline__ void stage_iter(char* xbuf, const float* xb_next,
                                           int tb_next, int s, int tid)
{
    const int ci = tid + (s << 7);           // s*128 threads
    if (ci < N_CHUNKS) {
        const int r  = ci >> 3;
        const int c8 = ci & 7;
        int rg = tb_next + r;
        if (rg > SEQ_LEN - 1) rg = SEQ_LEN - 1;   // halo clamp -> discarded t only
        const float4* src = (const float4*)(xb_next + (size_t)rg * 64 + c8 * 8);
        float4 v0 = src[0];
        float4 v1 = src[1];
        __half2 h0 = __floats2half2_rn(v0.x, v0.y);
        __half2 h1 = __floats2half2_rn(v0.z, v0.w);
        __half2 h2 = __floats2half2_rn(v1.x, v1.y);
        __half2 h3 = __floats2half2_rn(v1.z, v1.w);
        uint4 pk;
        pk.x = *(uint32_t*)&h0; pk.y = *(uint32_t*)&h1;
        pk.z = *(uint32_t*)&h2; pk.w = *(uint32_t*)&h3;
        *(uint4*)(xbuf + r * 128 + ((c8 ^ (r & 7)) * 16)) = pk;
    }
}

// ---------------- main kernel ----------------
// 4 warps/CTA, 2 CTAs/SM. Warp w owns rows [w*64, w*64+64) of the 256-row tile
// and all 64 filters (acc = 4 mt x 8 nt x 4 = 128 f32). B fragments come from
// L1-resident gmem scratch via LDG.128 (one per n-tile per kstep-pair). X is
// double-buffered in SMEM; next tile's staging is interleaved one iteration per
// kstep-pair. One __syncthreads per tile.
__global__ void __launch_bounds__(THREADS, 2)
conv1d_hmma_kernel(const float* __restrict__ x,
                   const float* __restrict__ bias,
                   float* __restrict__ out)
{
    extern __shared__ __align__(16) char smem[];
    const uint32_t smem_u = smem_to_u32(smem);
    const int tid  = threadIdx.x;
    const int lane = tid & 31;
    const int warp = tid >> 5;

    if (tid < N_F) ((float*)(smem + SMEM_BIAS))[tid] = bias[tid];

    // A ldmatrix lane mapping: lanes 0-15 -> rows, col-half 0; 16-31 -> half 1.
    const int arow0 = warp * 64 + (lane & 15);
    const int ahalf = lane >> 4;

    // B fragment base for this lane (uint4 index)
    const uint4* wfrag_lane = g_wfrag + lane;

    const int tile0 = blockIdx.x;   // GRID_CTAS < N_TILES always

    // ---- prologue: stage first tile into buffer 0 ----
    {
        const int batch = tile0 / TILES_PB;
        const int tb    = (tile0 % TILES_PB) * TILE_M;
        const float* xb = x + (size_t)batch * (SEQ_LEN * C_IN);
        for (int s = 0; s < STAGE_ITERS; s++)
            stage_iter(smem + SMEM_X0, xb, tb, s, tid);
    }
    __syncthreads();

    int cur = 0;
    for (int tile = tile0; tile < N_TILES; tile += GRID_CTAS) {
        const int batch = tile / TILES_PB;
        const int tb    = (tile % TILES_PB) * TILE_M;

        const int  tile_n   = tile + GRID_CTAS;
        const bool has_next = (tile_n < N_TILES);
        const int  batch_n  = has_next ? (tile_n / TILES_PB) : 0;
        const int  tb_n     = has_next ? ((tile_n % TILES_PB) * TILE_M) : 0;
        const float* xb_n   = x + (size_t)batch_n * (SEQ_LEN * C_IN);
        char* xbuf_next     = smem + (cur ? SMEM_X0 : SMEM_X1);
        const uint32_t xoff = cur ? SMEM_X1 : SMEM_X0;

        float acc[4][8][4];
        #pragma unroll
        for (int mt = 0; mt < 4; mt++)
            #pragma unroll
            for (int nt = 0; nt < 8; nt++)
                #pragma unroll
                for (int i = 0; i < 4; i++)
                    acc[mt][nt][i] = 0.0f;

        // ---- mainloop: 9 taps x 2 kstep-pairs ----
        #pragma unroll
        for (int tap = 0; tap < K_W; tap++) {
            #pragma unroll
            for (int half = 0; half < 2; half++) {
                const int sp = tap * 2 + half;

                // B fragments for both ksteps of this pair: 8 x LDG.128 (L1 hot)
                uint4 bv[8];
                #pragma unroll
                for (int j = 0; j < 8; j++)
                    bv[j] = wfrag_lane[(sp * 8 + j) * 32];

                // interleaved staging of next tile (17 iters over 18 slots)
                if (has_next && sp < STAGE_ITERS)
                    stage_iter(xbuf_next, xb_n, tb_n, sp, tid);

                #pragma unroll
                for (int kcin = 0; kcin < 2; kcin++) {
                    const int kc = half * 2 + kcin;
                    #pragma unroll
                    for (int mt = 0; mt < 4; mt++) {
                        const int row = arow0 + mt * 16 + tap;
                        const uint32_t chunk =
                            (uint32_t)((kc * 2 + ahalf) ^ (row & 7));
                        const uint32_t aaddr = smem_u + xoff
                            + (uint32_t)(row * 128) + chunk * 16;
                        uint32_t a0, a1, a2, a3;
                        LDSM_X4(a0, a1, a2, a3, aaddr);
                        #pragma unroll
                        for (int nt = 0; nt < 8; nt++) {
                            const uint32_t b0 = kcin ? bv[nt].z : bv[nt].x;
                            const uint32_t b1 = kcin ? bv[nt].w : bv[nt].y;
                            MMA_16816(acc[mt][nt], a0, a1, a2, a3, b0, b1);
                        }
                    }
                }
            }
        }

        // ---- epilogue: bias add + fp32 store ----
        const int trow0   = tb + warp * 64 + (lane >> 2);
        const int colbase = (lane & 3) * 2;
        const float* bsm  = (const float*)(smem + SMEM_BIAS);
        #pragma unroll
        for (int mt = 0; mt < 4; mt++) {
            #pragma unroll
            for (int h = 0; h < 2; h++) {
                const int t = trow0 + mt * 16 + h * 8;
                if (t < T_OUT) {
                    float* op = out + ((size_t)batch * T_OUT + t) * N_F;
                    #pragma unroll
                    for (int nt = 0; nt < 8; nt++) {
                        const int col = nt * 8 + colbase;
                        const float2 bvv = *(const float2*)(bsm + col);
                        float2 r2;
                        r2.x = acc[mt][nt][h * 2 + 0] + bvv.x;
                        r2.y = acc[mt][nt][h * 2 + 1] + bvv.y;
                        *(float2*)(op + col) = r2;
                    }
                }
            }
        }

        __syncthreads();   // staged writes visible; cur-buffer reads complete
        cur ^= 1;
    }
}

// ---------------- launch ----------------
extern "C" void kernel_launch(void* const* d_in, const int* in_sizes, int n_in,
                              void* d_out, int out_size)
{
    const float* x    = (const float*)d_in[0];
    const float* w    = (const float*)d_in[1];
    const float* bias = (const float*)d_in[2];
    float* out        = (float*)d_out;

    conv1d_wfrag_init<<<18, 256>>>(w);

    cudaFuncSetAttribute(conv1d_hmma_kernel,
                         cudaFuncAttributeMaxDynamicSharedMemorySize, SMEM_TOTAL);
    conv1d_hmma_kernel<<<GRID_CTAS, THREADS, SMEM_TOTAL>>>(x, bias, out);
}

// round 13
// speedup vs baseline: 1.1201x; 1.0496x over previous
#include <cuda_runtime.h>
#include <cuda_fp16.h>
#include <cstdint>

// ---------------- problem constants ----------------
#define SEQ_LEN   16384
#define T_OUT     16376
#define C_IN      64
#define N_F       64
#define K_W       9
#define N_BATCH   32

#define TILE_M    128
#define TILES_PB  (SEQ_LEN / TILE_M)       // 128
#define N_TILES   (N_BATCH * TILES_PB)     // 4096
#define GRID_CTAS 592                      // 148 SMs * 4 persistent CTAs
#define THREADS   128                      // 4 warps: (2 m-groups) x (2 n-halves)

// ---------------- SMEM layout ----------------
#define SMEM_BIAS  0                             // 256 B
#define SMEM_X0    256
#define X_ROWS     (TILE_M + 8)                  // 136 rows (tap halo)
#define XBUF_BYTES (X_ROWS * 128)                // 17408
#define SMEM_X1    (SMEM_X0 + XBUF_BYTES)
#define SMEM_TOTAL (SMEM_X1 + XBUF_BYTES)        // 35072 B -> 4 CTAs/SM

#define N_CHUNKS    (X_ROWS * 8)                 // 1088 16B-chunks per X buffer
#define STAGE_ITERS ((N_CHUNKS + THREADS - 1) / THREADS)   // 9

// ---------------- W fragment scratch (gmem, L1-resident) ----------------
// Layout: [sp(18)][j(8)][lane(32)] x 16B, sp = kstep pair, j = n-tile.
// 16B = { b0(s=2sp), b1(2sp), b0(2sp+1), b1(2sp+1) } as half2 each.
__device__ uint4 g_wfrag[18 * 8 * 32];           // 73728 B, stays hot in L1

__device__ __forceinline__ uint32_t smem_to_u32(const void* smem_ptr) {
    uint32_t addr;
    asm("{ .reg .u64 tmp; cvta.to.shared.u64 tmp, %1; cvt.u32.u64 %0, tmp; }"
        : "=r"(addr) : "l"(smem_ptr));
    return addr;
}

#define LDSM_X4(r0, r1, r2, r3, addr) \
    asm volatile("ldmatrix.sync.aligned.m8n8.x4.shared.b16 {%0,%1,%2,%3}, [%4];" \
        : "=r"(r0), "=r"(r1), "=r"(r2), "=r"(r3) : "r"(addr))

#define MMA_16816(acc, a0, a1, a2, a3, b0, b1) \
    asm volatile( \
        "mma.sync.aligned.m16n8k16.row.col.f32.f16.f16.f32 " \
        "{%0,%1,%2,%3}, {%4,%5,%6,%7}, {%8,%9}, {%0,%1,%2,%3};" \
        : "+f"((acc)[0]), "+f"((acc)[1]), "+f"((acc)[2]), "+f"((acc)[3]) \
        : "r"(a0), "r"(a1), "r"(a2), "r"(a3), "r"(b0), "r"(b1))

// ---------------- init kernel: pack W into fragment-major fp16 scratch ----------------
// mma.m16n8k16 B fragment (col-major KxN): lane holds b0 = (k=(lane%4)*2..+1,
// n=lane/4), b1 = (k+8, n). Global k = tap*64 + kc*16 + kk  (s = tap*4+kc).
__global__ void conv1d_wfrag_init(const float* __restrict__ w)
{
    const int idx  = blockIdx.x * 256 + threadIdx.x;   // 0..4607
    if (idx >= 18 * 8 * 32) return;
    const int lane = idx & 31;
    const int j    = (idx >> 5) & 7;
    const int sp   = idx >> 8;
    const int n    = j * 8 + (lane >> 2);
    uint32_t pk[4];
    #pragma unroll
    for (int e = 0; e < 2; e++) {
        const int s   = 2 * sp + e;
        const int tap = s >> 2;
        const int kc  = s & 3;
        const int c0  = kc * 16 + (lane & 3) * 2;
        const float* wr = w + (size_t)n * (K_W * C_IN) + tap * C_IN;
        __half2 b0 = __floats2half2_rn(wr[c0],     wr[c0 + 1]);
        __half2 b1 = __floats2half2_rn(wr[c0 + 8], wr[c0 + 9]);
        pk[2 * e]     = *(uint32_t*)&b0;
        pk[2 * e + 1] = *(uint32_t*)&b1;
    }
    uint4 v; v.x = pk[0]; v.y = pk[1]; v.z = pk[2]; v.w = pk[3];
    g_wfrag[idx] = v;
}

// One staging iteration: thread's s-th 16B chunk of the next tile's X buffer.
// Streaming loads (__ldcs) keep x out of L1 so the W fragment table stays hot.
__device__ __forceinline__ void stage_iter(char* xbuf, const float* xb_next,
                                           int tb_next, int s, int tid)
{
    const int ci = tid + (s << 7);           // s*128 threads
    if (ci < N_CHUNKS) {
        const int r  = ci >> 3;
        const int c8 = ci & 7;
        int rg = tb_next + r;
        if (rg > SEQ_LEN - 1) rg = SEQ_LEN - 1;   // halo clamp -> discarded t only
        const float4* src = (const float4*)(xb_next + (size_t)rg * 64 + c8 * 8);
        float4 v0 = __ldcs(src);
        float4 v1 = __ldcs(src + 1);
        __half2 h0 = __floats2half2_rn(v0.x, v0.y);
        __half2 h1 = __floats2half2_rn(v0.z, v0.w);
        __half2 h2 = __floats2half2_rn(v1.x, v1.y);
        __half2 h3 = __floats2half2_rn(v1.z, v1.w);
        uint4 pk;
        pk.x = *(uint32_t*)&h0; pk.y = *(uint32_t*)&h1;
        pk.z = *(uint32_t*)&h2; pk.w = *(uint32_t*)&h3;
        *(uint4*)(xbuf + r * 128 + ((c8 ^ (r & 7)) * 16)) = pk;
    }
}

// ---------------- main kernel ----------------
// 4 warps/CTA, 4 CTAs/SM (16 warps/SM = 4 per SMSP). Warp (wm, wn) owns rows
// [wm*64, wm*64+64) of the 128-row tile and filters [wn*32, wn*32+32):
// acc = 4 mt x 4 nt x 4 = 64 f32 regs -> no spills, deep latency hiding.
// B fragments via LDG.128 from L1-hot scratch. X double-buffered in SMEM with
// staging interleaved into the mainloop. One __syncthreads per tile.
__global__ void __launch_bounds__(THREADS, 4)
conv1d_hmma_kernel(const float* __restrict__ x,
                   const float* __restrict__ bias,
                   float* __restrict__ out)
{
    extern __shared__ __align__(16) char smem[];
    const uint32_t smem_u = smem_to_u32(smem);
    const int tid  = threadIdx.x;
    const int lane = tid & 31;
    const int warp = tid >> 5;
    const int wm   = warp >> 1;              // m-group: rows [wm*64, +64)
    const int wn   = warp & 1;               // n-half:  filters [wn*32, +32)

    if (tid < N_F) ((float*)(smem + SMEM_BIAS))[tid] = bias[tid];

    // A ldmatrix lane mapping: lanes 0-15 -> rows, col-half 0; 16-31 -> half 1.
    const int arow0 = wm * 64 + (lane & 15);
    const int ahalf = lane >> 4;

    // B fragment base for this lane/n-half (uint4 index into [sp][j][lane])
    const uint4* wfrag_lane = g_wfrag + (size_t)(wn * 4) * 32 + lane;

    const int tile0 = blockIdx.x;   // GRID_CTAS < N_TILES always

    // ---- prologue: stage first tile into buffer 0 ----
    {
        const int batch = tile0 >> 7;
        const int tb    = (tile0 & (TILES_PB - 1)) << 7;
        const float* xb = x + (size_t)batch * (SEQ_LEN * C_IN);
        for (int s = 0; s < STAGE_ITERS; s++)
            stage_iter(smem + SMEM_X0, xb, tb, s, tid);
    }
    __syncthreads();

    int cur = 0;
    for (int tile = tile0; tile < N_TILES; tile += GRID_CTAS) {
        const int batch = tile >> 7;
        const int tb    = (tile & (TILES_PB - 1)) << 7;

        const int  tile_n   = tile + GRID_CTAS;
        const bool has_next = (tile_n < N_TILES);
        const int  batch_n  = has_next ? (tile_n >> 7) : 0;
        const int  tb_n     = has_next ? ((tile_n & (TILES_PB - 1)) << 7) : 0;
        const float* xb_n   = x + (size_t)batch_n * (SEQ_LEN * C_IN);
        char* xbuf_next     = smem + (cur ? SMEM_X0 : SMEM_X1);
        const uint32_t xoff = cur ? SMEM_X1 : SMEM_X0;

        float acc[4][4][4];
        #pragma unroll
        for (int mt = 0; mt < 4; mt++)
            #pragma unroll
            for (int nt = 0; nt < 4; nt++)
                #pragma unroll
                for (int i = 0; i < 4; i++)
                    acc[mt][nt][i] = 0.0f;

        // ---- mainloop: 9 taps x 2 kstep-pairs ----
        #pragma unroll
        for (int tap = 0; tap < K_W; tap++) {
            #pragma unroll
            for (int half = 0; half < 2; half++) {
                const int sp = tap * 2 + half;

                // B fragments (this n-half, both ksteps): 4 x LDG.128, L1 hot
                uint4 bv[4];
                #pragma unroll
                for (int j = 0; j < 4; j++)
                    bv[j] = wfrag_lane[(sp * 8 + j) * 32];

                // interleaved staging of next tile (9 iters over 18 slots)
                if (has_next && !(sp & 1))
                    stage_iter(xbuf_next, xb_n, tb_n, sp >> 1, tid);

                #pragma unroll
                for (int kcin = 0; kcin < 2; kcin++) {
                    const int kc = half * 2 + kcin;
                    #pragma unroll
                    for (int mt = 0; mt < 4; mt++) {
                        const int row = arow0 + mt * 16 + tap;
                        const uint32_t chunk =
                            (uint32_t)((kc * 2 + ahalf) ^ (row & 7));
                        const uint32_t aaddr = smem_u + xoff
                            + (uint32_t)(row * 128) + chunk * 16;
                        uint32_t a0, a1, a2, a3;
                        LDSM_X4(a0, a1, a2, a3, aaddr);
                        #pragma unroll
                        for (int nt = 0; nt < 4; nt++) {
                            const uint32_t b0 = kcin ? bv[nt].z : bv[nt].x;
                            const uint32_t b1 = kcin ? bv[nt].w : bv[nt].y;
                            MMA_16816(acc[mt][nt], a0, a1, a2, a3, b0, b1);
                        }
                    }
                }
            }
        }

        // ---- epilogue: bias add + fp32 streaming store ----
        const int trow0   = tb + wm * 64 + (lane >> 2);
        const int colbase = wn * 32 + (lane & 3) * 2;
        const float* bsm  = (const float*)(smem + SMEM_BIAS);
        #pragma unroll
        for (int mt = 0; mt < 4; mt++) {
            #pragma unroll
            for (int h = 0; h < 2; h++) {
                const int t = trow0 + mt * 16 + h * 8;
                if (t < T_OUT) {
                    float* op = out + ((size_t)batch * T_OUT + t) * N_F;
                    #pragma unroll
                    for (int nt = 0; nt < 4; nt++) {
                        const int col = colbase + nt * 8;
                        const float2 bvv = *(const float2*)(bsm + col);
                        float2 r2;
                        r2.x = acc[mt][nt][h * 2 + 0] + bvv.x;
                        r2.y = acc[mt][nt][h * 2 + 1] + bvv.y;
                        __stcs((float2*)(op + col), r2);
                    }
                }
            }
        }

        __syncthreads();   // staged writes visible; cur-buffer reads complete
        cur ^= 1;
    }
}

// ---------------- launch ----------------
extern "C" void kernel_launch(void* const* d_in, const int* in_sizes, int n_in,
                              void* d_out, int out_size)
{
    const float* x    = (const float*)d_in[0];
    const float* w    = (const float*)d_in[1];
    const float* bias = (const float*)d_in[2];
    float* out        = (float*)d_out;

    conv1d_wfrag_init<<<18, 256>>>(w);

    cudaFuncSetAttribute(conv1d_hmma_kernel,
                         cudaFuncAttributeMaxDynamicSharedMemorySize, SMEM_TOTAL);
    conv1d_hmma_kernel<<<GRID_CTAS, THREADS, SMEM_TOTAL>>>(x, bias, out);
}